// round 15
// baseline (speedup 1.0000x reference)
#include <cuda_runtime.h>
#include <cuda_fp16.h>
#include <cstdint>

typedef unsigned long long ull;
#define EPSF 1e-6f

__device__ float   g_Q[24 * 128 * 128];
__device__ __half  g_Ah[(size_t)32768 * 1024];  // x as fp16
__device__ __half  g_Bh[(size_t)3072 * 1024];   // rotated W as fp16

__device__ __forceinline__ uint32_t smem_u32(const void* p) {
    uint32_t a;
    asm("{ .reg .u64 t; cvta.to.shared.u64 t, %1; cvt.u32.u64 %0, t; }" : "=r"(a) : "l"(p));
    return a;
}
__device__ __forceinline__ void cpa16(uint32_t s, const void* g) {
    asm volatile("cp.async.cg.shared.global [%0], [%1], 16;" :: "r"(s), "l"(g));
}
#define CP_COMMIT() asm volatile("cp.async.commit_group;")

// swizzled byte offset of element (row, k) in a [rows][64] fp16 tile, 128B rows.
#define OFFS64(row, k) ((uint32_t)((row) * 128 + (((((k) >> 3) ^ ((row) & 7))) << 4)))

#define LDSM4(r, ad) \
    asm volatile("ldmatrix.sync.aligned.m8n8.x4.shared.b16 {%0,%1,%2,%3}, [%4];" \
        : "=r"((r)[0]), "=r"((r)[1]), "=r"((r)[2]), "=r"((r)[3]) : "r"(ad))

#define MMA(cc, A, b0, b1) \
    asm volatile("mma.sync.aligned.m16n8k16.row.col.f32.f16.f16.f32 " \
        "{%0,%1,%2,%3},{%4,%5,%6,%7},{%8,%9},{%0,%1,%2,%3};" \
        : "+f"((cc)[0]), "+f"((cc)[1]), "+f"((cc)[2]), "+f"((cc)[3]) \
        : "r"((A)[0]), "r"((A)[1]), "r"((A)[2]), "r"((A)[3]), "r"(b0), "r"(b1))

// ===========================================================================
// prep: blocks 0-23 cayley (register GJ, static unroll); blocks 24+ convert.
// ===========================================================================
__global__ __launch_bounds__(512)
void prep_kernel(const float* __restrict__ qR, const float* __restrict__ kR,
                 const float* __restrict__ vR, const float* __restrict__ x) {
    const int tid = threadIdx.x;
    if (blockIdx.x >= 24) {
        const float4* xv = (const float4*)x;
        const size_t stride = (size_t)1024 * 512;
        for (size_t u = (size_t)(blockIdx.x - 24) * 512 + tid;
             u < (size_t)32768 * 128; u += stride) {
            float4 a = xv[2 * u];
            float4 b = xv[2 * u + 1];
            uint4 hv;
            __half2 h0 = __floats2half2_rn(a.x, a.y);
            __half2 h1 = __floats2half2_rn(a.z, a.w);
            __half2 h2 = __floats2half2_rn(b.x, b.y);
            __half2 h3 = __floats2half2_rn(b.z, b.w);
            hv.x = *(uint32_t*)&h0; hv.y = *(uint32_t*)&h1;
            hv.z = *(uint32_t*)&h2; hv.w = *(uint32_t*)&h3;
            *(uint4*)(&g_Ah[u * 8]) = hv;
        }
        return;
    }
    // ---- cayley: Q = (2+eps)*inv(I+S+epsI) - I ----
    __shared__ float rowb[2][132];
    __shared__ float colb[2][128];
    const int idx  = blockIdx.x;
    const int proj = idx >> 3, n = idx & 7;
    const float* src = (proj == 0 ? qR : (proj == 1 ? kR : vR)) + n * 16384;
    const int r = tid & 127, q = tid >> 7, c0 = q * 32;

    float regs[32];
    #pragma unroll
    for (int j = 0; j < 32; ++j) {
        int c = c0 + j;
        float v = 0.5f * (src[r * 128 + c] - src[c * 128 + r]);
        if (c == r) v += 1.0f + EPSF;
        regs[j] = v;
    }
    if (r == 0) {
        #pragma unroll
        for (int j = 0; j < 32; ++j) rowb[0][c0 + j] = regs[j];
    }
    if (q == 0) colb[0][r] = regs[0];

    for (int kb = 0; kb < 4; ++kb) {
        const bool ownq  = (q == kb);
        const bool nextq = (q == kb + 1);
        #pragma unroll
        for (int kk = 0; kk < 32; ++kk) {
            const int k = kb * 32 + kk;
            const int b = k & 1, nb = b ^ 1;
            __syncthreads();
            const float pivinv = 1.0f / rowb[b][k];
            const float f      = colb[b][r];
            if (r == k) {
                #pragma unroll
                for (int j = 0; j < 32; ++j) regs[j] *= pivinv;
                if (ownq) regs[kk] = pivinv;
            } else {
                const float t = f * pivinv;
                const float4* rp = (const float4*)&rowb[b][c0];
                #pragma unroll
                for (int v4 = 0; v4 < 8; ++v4) {
                    float4 rv = rp[v4];
                    regs[4 * v4 + 0] = fmaf(-t, rv.x, regs[4 * v4 + 0]);
                    regs[4 * v4 + 1] = fmaf(-t, rv.y, regs[4 * v4 + 1]);
                    regs[4 * v4 + 2] = fmaf(-t, rv.z, regs[4 * v4 + 2]);
                    regs[4 * v4 + 3] = fmaf(-t, rv.w, regs[4 * v4 + 3]);
                }
                if (ownq) regs[kk] = -t;
            }
            if (k < 127) {
                if (r == k + 1) {
                    float4* wp = (float4*)&rowb[nb][c0];
                    #pragma unroll
                    for (int v4 = 0; v4 < 8; ++v4)
                        wp[v4] = make_float4(regs[4 * v4 + 0], regs[4 * v4 + 1],
                                             regs[4 * v4 + 2], regs[4 * v4 + 3]);
                }
                if (kk < 31) { if (ownq)  colb[nb][r] = regs[kk + 1]; }
                else         { if (nextq) colb[nb][r] = regs[0]; }
            }
        }
    }
    float* dst = g_Q + idx * 16384 + r * 128 + c0;
    const float s = 2.0f + EPSF;
    #pragma unroll
    for (int j = 0; j < 32; ++j) {
        float v = s * regs[j];
        if (c0 + j == r) v -= 1.0f;
        dst[j] = v;
    }
}

// ===========================================================================
// rotate: Wrot = W_block @ Q, fp16 output. 192 CTAs.
// ===========================================================================
__global__ __launch_bounds__(256)
void rotate_kernel(const float* __restrict__ W) {
    extern __shared__ float Qs[];
    const int tid = threadIdx.x;
    const int b   = blockIdx.x;
    const int idx = b >> 3, oy = b & 7;
    const int proj = idx >> 3, n = idx & 7;
    const int obase = proj * 1024 + oy * 128;
    const int cbase = n * 128;
    for (int i = tid; i < 16384; i += 256) Qs[i] = g_Q[idx * 16384 + i];
    __syncthreads();
    const int c = tid & 127, half = tid >> 7;
    const float* Wp = W + (size_t)obase * 1024 + cbase;
    for (int oc = half * 64; oc < half * 64 + 64; oc += 4) {
        float acc[4] = {0.f, 0.f, 0.f, 0.f};
        #pragma unroll 4
        for (int bb = 0; bb < 128; ++bb) {
            float qv = Qs[bb * 128 + c];
            acc[0] = fmaf(Wp[(size_t)(oc + 0) * 1024 + bb], qv, acc[0]);
            acc[1] = fmaf(Wp[(size_t)(oc + 1) * 1024 + bb], qv, acc[1]);
            acc[2] = fmaf(Wp[(size_t)(oc + 2) * 1024 + bb], qv, acc[2]);
            acc[3] = fmaf(Wp[(size_t)(oc + 3) * 1024 + bb], qv, acc[3]);
        }
        #pragma unroll
        for (int u = 0; u < 4; ++u)
            g_Bh[(size_t)(obase + oc + u) * 1024 + cbase + c] = __float2half_rn(acc[u]);
    }
}

// ===========================================================================
// gemm: single-pass fp16 mma.sync. CTA 128x256, 512 threads (16 warps,
// warp tile 64x32), K chunks of 64, 4 stages (48KB each), occupancy 1.
// Bigger N tile cuts L2 tile traffic 3.2GB -> 2.3GB (under the LTS cap).
// ===========================================================================
#define STAGE_B 49152
#define GEMM_SMEM (4 * STAGE_B)

__global__ __launch_bounds__(512, 1)
void gemm_kernel(const float* __restrict__ bias, float* __restrict__ out) {
    extern __shared__ char smem[];
    const uint32_t sb = smem_u32(smem);
    const int tid = threadIdx.x, wid = tid >> 5, lane = tid & 31;
    const int m0 = blockIdx.y * 128, n0 = blockIdx.x * 256;
    const int wm = (wid >> 3) * 64, wn = (wid & 7) * 32;

    float c[4][4][4];
    #pragma unroll
    for (int i = 0; i < 4; ++i)
        #pragma unroll
        for (int j = 0; j < 4; ++j)
            #pragma unroll
            for (int t = 0; t < 4; ++t) c[i][j][t] = 0.f;

    // loaders: A 128x64 (2 xfers/thread), B 256x64 (4 xfers/thread)
    uint32_t soA[2]; const char* gAu[2];
    #pragma unroll
    for (int u = 0; u < 2; ++u) {
        int id = tid + 512 * u;
        int row = id >> 3, kg = id & 7;
        soA[u] = (uint32_t)(row * 128 + ((kg ^ (row & 7)) << 4));
        gAu[u] = (const char*)g_Ah + (size_t)(m0 + row) * 2048 + kg * 16;
    }
    uint32_t soB[4]; const char* gBu[4];
    #pragma unroll
    for (int u = 0; u < 4; ++u) {
        int id = tid + 512 * u;
        int row = id >> 3, kg = id & 7;
        soB[u] = (uint32_t)(row * 128 + ((kg ^ (row & 7)) << 4));
        gBu[u] = (const char*)g_Bh + (size_t)(n0 + row) * 2048 + kg * 16;
    }

#define ISSUE(kt) do { \
    uint32_t st = sb + ((kt) % 4) * STAGE_B; \
    size_t gk = (size_t)(kt) * 128; \
    _Pragma("unroll") \
    for (int u = 0; u < 2; ++u) cpa16(st + soA[u], gAu[u] + gk); \
    _Pragma("unroll") \
    for (int u = 0; u < 4; ++u) cpa16(st + 16384 + soB[u], gBu[u] + gk); \
    CP_COMMIT(); \
} while (0)

#define KS_BODY(ks) do { \
    uint32_t a[4][4], bf[2][4]; \
    _Pragma("unroll") \
    for (int i = 0; i < 4; ++i) LDSM4(a[i], stA + OFFS64(arow + i * 16, (ks) + akb)); \
    _Pragma("unroll") \
    for (int p = 0; p < 2; ++p) LDSM4(bf[p], stB + OFFS64(bnr + p * 16, (ks) + bkb)); \
    _Pragma("unroll") \
    for (int i = 0; i < 4; ++i) { \
        MMA(c[i][0], a[i], bf[0][0], bf[0][1]); \
        MMA(c[i][1], a[i], bf[0][2], bf[0][3]); \
        MMA(c[i][2], a[i], bf[1][0], bf[1][1]); \
        MMA(c[i][3], a[i], bf[1][2], bf[1][3]); \
    } \
} while (0)

    ISSUE(0);
    ISSUE(1);
    ISSUE(2);

    const int arow = wm + (lane & 7) + ((lane >> 3) & 1) * 8;
    const int akb  = ((lane >> 4) & 1) * 8;
    const int bnr  = wn + (lane & 7) + ((lane >> 4) & 1) * 8;
    const int bkb  = ((lane >> 3) & 1) * 8;

    for (int kt = 0; kt < 16; ++kt) {
        if (kt < 14)      asm volatile("cp.async.wait_group 2;");
        else if (kt == 14) asm volatile("cp.async.wait_group 1;");
        else               asm volatile("cp.async.wait_group 0;");
        __syncthreads();
        const uint32_t stA = sb + (kt % 4) * STAGE_B;
        const uint32_t stB = stA + 16384;

        KS_BODY(0);
        KS_BODY(16);
        if (kt + 3 < 16) ISSUE(kt + 3);
        KS_BODY(32);
        KS_BODY(48);
        __syncthreads();   // all reads of slot (kt%4) done before refill
    }

    float2 bj[4];
    #pragma unroll
    for (int j = 0; j < 4; ++j)
        bj[j] = *(const float2*)(bias + n0 + wn + j * 8 + (lane & 3) * 2);

    #pragma unroll
    for (int i = 0; i < 4; ++i) {
        const int r = m0 + wm + i * 16 + (lane >> 2);
        #pragma unroll
        for (int j = 0; j < 4; ++j) {
            const int col = n0 + wn + j * 8 + (lane & 3) * 2;
            float2 v0 = {c[i][j][0] + bj[j].x, c[i][j][1] + bj[j].y};
            float2 v1 = {c[i][j][2] + bj[j].x, c[i][j][3] + bj[j].y};
            *(float2*)(out + (size_t)r * 3072 + col)       = v0;
            *(float2*)(out + (size_t)(r + 8) * 3072 + col) = v1;
        }
    }
}

// ---------------------------------------------------------------------------
extern "C" void kernel_launch(void* const* d_in, const int* in_sizes, int n_in,
                              void* d_out, int out_size) {
    const float* W    = (const float*)d_in[0];
    const float* bias = (const float*)d_in[1];
    const float* x    = (const float*)d_in[2];
    const float* qR   = (const float*)d_in[3];
    const float* kR   = (const float*)d_in[4];
    const float* vR   = (const float*)d_in[5];
    float* out = (float*)d_out;

    cudaFuncSetAttribute(rotate_kernel, cudaFuncAttributeMaxDynamicSharedMemorySize, 65536);
    cudaFuncSetAttribute(gemm_kernel,   cudaFuncAttributeMaxDynamicSharedMemorySize, GEMM_SMEM);

    prep_kernel<<<24 + 1024, 512>>>(qR, kR, vR, x);
    rotate_kernel<<<192, 256, 65536>>>(W);
    gemm_kernel<<<dim3(12, 256), 512, GEMM_SMEM>>>(bias, out);
}

// round 16
// speedup vs baseline: 1.1884x; 1.1884x over previous
#include <cuda_runtime.h>
#include <cuda_fp16.h>
#include <cstdint>

typedef unsigned long long ull;
#define EPSF 1e-6f

__device__ float   g_Q[24 * 128 * 128];
__device__ __half  g_Ah[(size_t)32768 * 1024];  // x as fp16
__device__ __half  g_Bh[(size_t)3072 * 1024];   // rotated W as fp16

__device__ __forceinline__ uint32_t smem_u32(const void* p) {
    uint32_t a;
    asm("{ .reg .u64 t; cvta.to.shared.u64 t, %1; cvt.u32.u64 %0, t; }" : "=r"(a) : "l"(p));
    return a;
}
__device__ __forceinline__ void cpa16(uint32_t s, const void* g) {
    asm volatile("cp.async.cg.shared.global [%0], [%1], 16;" :: "r"(s), "l"(g));
}
#define CP_COMMIT() asm volatile("cp.async.commit_group;")

// swizzled byte offset of element (row, k) in a [128][64] fp16 tile, 128B rows.
#define OFFS64(row, k) ((uint32_t)((row) * 128 + (((((k) >> 3) ^ ((row) & 7))) << 4)))

#define LDSM4(r, ad) \
    asm volatile("ldmatrix.sync.aligned.m8n8.x4.shared.b16 {%0,%1,%2,%3}, [%4];" \
        : "=r"((r)[0]), "=r"((r)[1]), "=r"((r)[2]), "=r"((r)[3]) : "r"(ad))

#define MMA(cc, A, b0, b1) \
    asm volatile("mma.sync.aligned.m16n8k16.row.col.f32.f16.f16.f32 " \
        "{%0,%1,%2,%3},{%4,%5,%6,%7},{%8,%9},{%0,%1,%2,%3};" \
        : "+f"((cc)[0]), "+f"((cc)[1]), "+f"((cc)[2]), "+f"((cc)[3]) \
        : "r"((A)[0]), "r"((A)[1]), "r"((A)[2]), "r"((A)[3]), "r"(b0), "r"(b1))

// ===========================================================================
// prep: blocks 0-23 cayley (register GJ, static unroll); blocks 24+ convert.
// ===========================================================================
__global__ __launch_bounds__(512)
void prep_kernel(const float* __restrict__ qR, const float* __restrict__ kR,
                 const float* __restrict__ vR, const float* __restrict__ x) {
    const int tid = threadIdx.x;
    if (blockIdx.x >= 24) {
        const float4* xv = (const float4*)x;
        const size_t stride = (size_t)1024 * 512;
        const size_t total  = (size_t)32768 * 128;
        size_t u = (size_t)(blockIdx.x - 24) * 512 + tid;
        for (; u + stride < total; u += 2 * stride) {
            // two independent iterations in flight (MLP)
            float4 a0 = xv[2 * u],            b0 = xv[2 * u + 1];
            float4 a1 = xv[2 * (u + stride)], b1 = xv[2 * (u + stride) + 1];
            uint4 hv0, hv1;
            __half2 t0 = __floats2half2_rn(a0.x, a0.y);
            __half2 t1 = __floats2half2_rn(a0.z, a0.w);
            __half2 t2 = __floats2half2_rn(b0.x, b0.y);
            __half2 t3 = __floats2half2_rn(b0.z, b0.w);
            hv0.x = *(uint32_t*)&t0; hv0.y = *(uint32_t*)&t1;
            hv0.z = *(uint32_t*)&t2; hv0.w = *(uint32_t*)&t3;
            __half2 s0 = __floats2half2_rn(a1.x, a1.y);
            __half2 s1 = __floats2half2_rn(a1.z, a1.w);
            __half2 s2 = __floats2half2_rn(b1.x, b1.y);
            __half2 s3 = __floats2half2_rn(b1.z, b1.w);
            hv1.x = *(uint32_t*)&s0; hv1.y = *(uint32_t*)&s1;
            hv1.z = *(uint32_t*)&s2; hv1.w = *(uint32_t*)&s3;
            *(uint4*)(&g_Ah[u * 8])            = hv0;
            *(uint4*)(&g_Ah[(u + stride) * 8]) = hv1;
        }
        if (u < total) {
            float4 a = xv[2 * u], b = xv[2 * u + 1];
            uint4 hv;
            __half2 h0 = __floats2half2_rn(a.x, a.y);
            __half2 h1 = __floats2half2_rn(a.z, a.w);
            __half2 h2 = __floats2half2_rn(b.x, b.y);
            __half2 h3 = __floats2half2_rn(b.z, b.w);
            hv.x = *(uint32_t*)&h0; hv.y = *(uint32_t*)&h1;
            hv.z = *(uint32_t*)&h2; hv.w = *(uint32_t*)&h3;
            *(uint4*)(&g_Ah[u * 8]) = hv;
        }
        return;
    }
    // ---- cayley: Q = (2+eps)*inv(I+S+epsI) - I ----
    __shared__ float rowb[2][132];
    __shared__ float colb[2][128];
    const int idx  = blockIdx.x;
    const int proj = idx >> 3, n = idx & 7;
    const float* src = (proj == 0 ? qR : (proj == 1 ? kR : vR)) + n * 16384;
    const int r = tid & 127, q = tid >> 7, c0 = q * 32;

    float regs[32];
    #pragma unroll
    for (int j = 0; j < 32; ++j) {
        int c = c0 + j;
        float v = 0.5f * (src[r * 128 + c] - src[c * 128 + r]);
        if (c == r) v += 1.0f + EPSF;
        regs[j] = v;
    }
    if (r == 0) {
        #pragma unroll
        for (int j = 0; j < 32; ++j) rowb[0][c0 + j] = regs[j];
    }
    if (q == 0) colb[0][r] = regs[0];

    for (int kb = 0; kb < 4; ++kb) {
        const bool ownq  = (q == kb);
        const bool nextq = (q == kb + 1);
        #pragma unroll
        for (int kk = 0; kk < 32; ++kk) {
            const int k = kb * 32 + kk;
            const int b = k & 1, nb = b ^ 1;
            __syncthreads();
            const float pivinv = 1.0f / rowb[b][k];
            const float f      = colb[b][r];
            if (r == k) {
                #pragma unroll
                for (int j = 0; j < 32; ++j) regs[j] *= pivinv;
                if (ownq) regs[kk] = pivinv;
            } else {
                const float t = f * pivinv;
                const float4* rp = (const float4*)&rowb[b][c0];
                #pragma unroll
                for (int v4 = 0; v4 < 8; ++v4) {
                    float4 rv = rp[v4];
                    regs[4 * v4 + 0] = fmaf(-t, rv.x, regs[4 * v4 + 0]);
                    regs[4 * v4 + 1] = fmaf(-t, rv.y, regs[4 * v4 + 1]);
                    regs[4 * v4 + 2] = fmaf(-t, rv.z, regs[4 * v4 + 2]);
                    regs[4 * v4 + 3] = fmaf(-t, rv.w, regs[4 * v4 + 3]);
                }
                if (ownq) regs[kk] = -t;
            }
            if (k < 127) {
                if (r == k + 1) {
                    float4* wp = (float4*)&rowb[nb][c0];
                    #pragma unroll
                    for (int v4 = 0; v4 < 8; ++v4)
                        wp[v4] = make_float4(regs[4 * v4 + 0], regs[4 * v4 + 1],
                                             regs[4 * v4 + 2], regs[4 * v4 + 3]);
                }
                if (kk < 31) { if (ownq)  colb[nb][r] = regs[kk + 1]; }
                else         { if (nextq) colb[nb][r] = regs[0]; }
            }
        }
    }
    float* dst = g_Q + idx * 16384 + r * 128 + c0;
    const float s = 2.0f + EPSF;
    #pragma unroll
    for (int j = 0; j < 32; ++j) {
        float v = s * regs[j];
        if (c0 + j == r) v -= 1.0f;
        dst[j] = v;
    }
}

// ===========================================================================
// rotate: Wrot = W_block @ Q, fp16 output. 384 CTAs (64 output rows each).
// ===========================================================================
__global__ __launch_bounds__(256)
void rotate_kernel(const float* __restrict__ W) {
    extern __shared__ float Qs[];
    const int tid = threadIdx.x;
    const int b   = blockIdx.x;           // 0..383
    const int idx = b >> 4;               // 0..23 (proj, n)
    const int sub = b & 15;               // 16 sub-tiles
    const int oy  = sub >> 1;             // 0..7 (128-row block)
    const int oh  = sub & 1;              // which 64-row half
    const int proj = idx >> 3, n = idx & 7;
    const int obase = proj * 1024 + oy * 128 + oh * 64;
    const int cbase = n * 128;
    for (int i = tid; i < 16384; i += 256) Qs[i] = g_Q[idx * 16384 + i];
    __syncthreads();
    const int c = tid & 127, half = tid >> 7;
    const float* Wp = W + (size_t)obase * 1024 + cbase;
    for (int oc = half * 32; oc < half * 32 + 32; oc += 4) {
        float acc[4] = {0.f, 0.f, 0.f, 0.f};
        #pragma unroll 4
        for (int bb = 0; bb < 128; ++bb) {
            float qv = Qs[bb * 128 + c];
            acc[0] = fmaf(Wp[(size_t)(oc + 0) * 1024 + bb], qv, acc[0]);
            acc[1] = fmaf(Wp[(size_t)(oc + 1) * 1024 + bb], qv, acc[1]);
            acc[2] = fmaf(Wp[(size_t)(oc + 2) * 1024 + bb], qv, acc[2]);
            acc[3] = fmaf(Wp[(size_t)(oc + 3) * 1024 + bb], qv, acc[3]);
        }
        #pragma unroll
        for (int u = 0; u < 4; ++u)
            g_Bh[(size_t)(obase + oc + u) * 1024 + cbase + c] = __float2half_rn(acc[u]);
    }
}

// ===========================================================================
// gemm: single-pass fp16 mma.sync. CTA 128x128, K chunks of 64, 3 stages
// (32KB each), occupancy 2, one barrier per chunk.  (R14 config — best known)
// ===========================================================================
#define STAGE_B 32768
#define GEMM_SMEM (3 * STAGE_B)

__global__ __launch_bounds__(256, 2)
void gemm_kernel(const float* __restrict__ bias, float* __restrict__ out) {
    extern __shared__ char smem[];
    const uint32_t sb = smem_u32(smem);
    const int tid = threadIdx.x, wid = tid >> 5, lane = tid & 31;
    const int m0 = blockIdx.y * 128, n0 = blockIdx.x * 128;
    const int wm = (wid >> 2) * 64, wn = (wid & 3) * 32;

    float c[4][4][4];
    #pragma unroll
    for (int i = 0; i < 4; ++i)
        #pragma unroll
        for (int j = 0; j < 4; ++j)
            #pragma unroll
            for (int t = 0; t < 4; ++t) c[i][j][t] = 0.f;

    // loader geometry: per u, id = tid + 256u -> row = id>>3 (0..127), kg = id&7
    uint32_t soU[4];
    const char* gAu[4];
    const char* gBu[4];
    #pragma unroll
    for (int u = 0; u < 4; ++u) {
        int id  = tid + 256 * u;
        int row = id >> 3, kg = id & 7;
        soU[u] = (uint32_t)(row * 128 + ((kg ^ (row & 7)) << 4));
        gAu[u] = (const char*)g_Ah + (size_t)(m0 + row) * 2048 + kg * 16;
        gBu[u] = (const char*)g_Bh + (size_t)(n0 + row) * 2048 + kg * 16;
    }

#define ISSUE(kt) do { \
    uint32_t st = sb + ((kt) % 3) * STAGE_B; \
    size_t gk = (size_t)(kt) * 128; \
    _Pragma("unroll") \
    for (int u = 0; u < 4; ++u) { \
        cpa16(st + soU[u],         gAu[u] + gk); \
        cpa16(st + 16384 + soU[u], gBu[u] + gk); \
    } \
    CP_COMMIT(); \
} while (0)

#define KS_BODY(ks) do { \
    uint32_t a[4][4], bf[2][4]; \
    _Pragma("unroll") \
    for (int i = 0; i < 4; ++i) LDSM4(a[i], stA + OFFS64(arow + i * 16, (ks) + akb)); \
    _Pragma("unroll") \
    for (int p = 0; p < 2; ++p) LDSM4(bf[p], stB + OFFS64(bnr + p * 16, (ks) + bkb)); \
    _Pragma("unroll") \
    for (int i = 0; i < 4; ++i) { \
        MMA(c[i][0], a[i], bf[0][0], bf[0][1]); \
        MMA(c[i][1], a[i], bf[0][2], bf[0][3]); \
        MMA(c[i][2], a[i], bf[1][0], bf[1][1]); \
        MMA(c[i][3], a[i], bf[1][2], bf[1][3]); \
    } \
} while (0)

    ISSUE(0);
    ISSUE(1);

    const int arow = wm + (lane & 7) + ((lane >> 3) & 1) * 8;
    const int akb  = ((lane >> 4) & 1) * 8;
    const int bnr  = wn + (lane & 7) + ((lane >> 4) & 1) * 8;
    const int bkb  = ((lane >> 3) & 1) * 8;

    for (int kt = 0; kt < 16; ++kt) {
        if (kt < 15) asm volatile("cp.async.wait_group 1;");
        else         asm volatile("cp.async.wait_group 0;");
        __syncthreads();
        const uint32_t stA = sb + (kt % 3) * STAGE_B;
        const uint32_t stB = stA + 16384;

        KS_BODY(0);
        KS_BODY(16);
        if (kt + 2 < 16) ISSUE(kt + 2);
        KS_BODY(32);
        KS_BODY(48);
    }

    float2 bj[4];
    #pragma unroll
    for (int j = 0; j < 4; ++j)
        bj[j] = *(const float2*)(bias + n0 + wn + j * 8 + (lane & 3) * 2);

    #pragma unroll
    for (int i = 0; i < 4; ++i) {
        const int r = m0 + wm + i * 16 + (lane >> 2);
        #pragma unroll
        for (int j = 0; j < 4; ++j) {
            const int col = n0 + wn + j * 8 + (lane & 3) * 2;
            float2 v0 = {c[i][j][0] + bj[j].x, c[i][j][1] + bj[j].y};
            float2 v1 = {c[i][j][2] + bj[j].x, c[i][j][3] + bj[j].y};
            *(float2*)(out + (size_t)r * 3072 + col)       = v0;
            *(float2*)(out + (size_t)(r + 8) * 3072 + col) = v1;
        }
    }
}

// ---------------------------------------------------------------------------
extern "C" void kernel_launch(void* const* d_in, const int* in_sizes, int n_in,
                              void* d_out, int out_size) {
    const float* W    = (const float*)d_in[0];
    const float* bias = (const float*)d_in[1];
    const float* x    = (const float*)d_in[2];
    const float* qR   = (const float*)d_in[3];
    const float* kR   = (const float*)d_in[4];
    const float* vR   = (const float*)d_in[5];
    float* out = (float*)d_out;

    cudaFuncSetAttribute(rotate_kernel, cudaFuncAttributeMaxDynamicSharedMemorySize, 65536);
    cudaFuncSetAttribute(gemm_kernel,   cudaFuncAttributeMaxDynamicSharedMemorySize, GEMM_SMEM);

    prep_kernel<<<24 + 1024, 512>>>(qR, kR, vR, x);
    rotate_kernel<<<384, 256, 65536>>>(W);
    gemm_kernel<<<dim3(24, 256), 256, GEMM_SMEM>>>(bias, out);
}